// round 1
// baseline (speedup 1.0000x reference)
#include <cuda_runtime.h>
#include <cstdint>

#define BB 4
#define SS 512
#define DD 128
#define HH 8
#define SC_PITCH 516   // 516 % 32 == 4 -> 8 head lanes (stride 4 banks) conflict-free

// scratch (static device memory; no runtime allocation)
__device__ float g_q[BB*SS*DD];
__device__ float g_k[BB*SS*DD];
__device__ float g_v[BB*SS*DD];
__device__ float g_attn[BB*SS*DD];

// ---------------------------------------------------------------------------
// Kernel A: QKV projection. grid=256 (8 rows/block), block=384 (128 per matrix)
// ---------------------------------------------------------------------------
__global__ __launch_bounds__(384) void qkv_kernel(
    const float* __restrict__ x,
    const float* __restrict__ wq, const float* __restrict__ bq,
    const float* __restrict__ wk, const float* __restrict__ bk,
    const float* __restrict__ wv, const float* __restrict__ bv)
{
    __shared__ float xs[8][128];
    const int row0 = blockIdx.x * 8;
    const int t = threadIdx.x;

    if (t < 256) ((float4*)xs)[t] = ((const float4*)(x + (size_t)row0 * DD))[t];
    __syncthreads();

    const int mat = t >> 7;      // 0=q 1=k 2=v
    const int c   = t & 127;
    const float* W    = (mat == 0) ? wq : (mat == 1) ? wk : wv;
    const float* bias = (mat == 0) ? bq : (mat == 1) ? bk : bv;
    float* out        = (mat == 0) ? g_q : (mat == 1) ? g_k : g_v;

    float acc[8];
    #pragma unroll
    for (int r = 0; r < 8; r++) acc[r] = 0.f;

    #pragma unroll 8
    for (int d = 0; d < 128; d++) {
        float w = W[d * 128 + c];
        #pragma unroll
        for (int r = 0; r < 8; r++) acc[r] = fmaf(xs[r][d], w, acc[r]);
    }
    float bv_ = bias[c];
    #pragma unroll
    for (int r = 0; r < 8; r++) out[(size_t)(row0 + r) * DD + c] = acc[r] + bv_;
}

// ---------------------------------------------------------------------------
// Kernel B: fused st-bias + attention.
// grid = 256 (b = bx>>6, q0 = (bx&63)*8), block = 512, ~172KB dyn smem
// ---------------------------------------------------------------------------
__global__ __launch_bounds__(512, 1) void attn_kernel(
    const float* __restrict__ st, const int* __restrict__ mask,
    const float* __restrict__ wst)
{
    extern __shared__ float smem[];
    float* scores = smem;                               // [8][8][SC_PITCH]
    float* qs     = scores + 8 * 8 * SC_PITCH;          // [8][128]
    float* mask_s = qs + 8 * 128;                       // [512]
    float* rinv_s = mask_s + 512;                       // [64] (q*8+h)
    float* ks     = rinv_s + 64;                        // [64][129]; reused as outp[2][8][8][16]

    const int tid  = threadIdx.x;
    const int lane = tid & 31;
    const int wid  = tid >> 5;
    const int b    = blockIdx.x >> 6;
    const int q0   = (blockIdx.x & 63) * 8;

    // wst into registers: this lane owns d = 4*lane .. 4*lane+3
    float wreg[4][8];
    #pragma unroll
    for (int dd = 0; dd < 4; dd++)
        #pragma unroll
        for (int h = 0; h < 8; h++)
            wreg[dd][h] = wst[(4 * lane + dd) * HH + h];

    // stage q tile + mask
    if (tid < 256)
        ((float4*)qs)[tid] = ((const float4*)(g_q + (size_t)(b * SS + q0) * DD))[tid];
    mask_s[tid] = mask[b * SS + tid] ? -10000.0f : 0.0f;
    __syncthreads();

    // ---------------- Phase 1: qk^T / 4 into scores ----------------
    {
        const int q  = tid >> 6;   // 0..7
        const int kl = tid & 63;   // 0..63
        for (int kc = 0; kc < 8; kc++) {
            const float4* kg = (const float4*)(g_k + (size_t)(b * SS + kc * 64) * DD);
            #pragma unroll
            for (int idx = tid; idx < 64 * 32; idx += 512) {
                int r = idx >> 5, c4 = idx & 31;
                float4 kv = kg[r * 32 + c4];
                float* dst = ks + r * 129 + c4 * 4;
                dst[0] = kv.x; dst[1] = kv.y; dst[2] = kv.z; dst[3] = kv.w;
            }
            __syncthreads();

            float acc[8];
            #pragma unroll
            for (int h = 0; h < 8; h++) acc[h] = 0.f;
            const float* krow = ks + kl * 129;
            const float* qrow = qs + q * 128;
            #pragma unroll
            for (int e = 0; e < 128; e++)
                acc[e >> 4] = fmaf(qrow[e], krow[e], acc[e >> 4]);

            float* sdst = scores + (q * 8) * SC_PITCH + kc * 64 + kl;
            #pragma unroll
            for (int h = 0; h < 8; h++) sdst[h * SC_PITCH] = acc[h] * 0.25f;
            __syncthreads();
        }
    }

    // ---------------- Phase 2: st_emb bias (the 536MB stream) ----------------
    {
        // row (q*512+k) == task t; address = base + t*128 floats
        const float4* st4 = (const float4*)st + ((size_t)(b * SS + q0)) * SS * (DD / 4);
        float4 E[4];
        #pragma unroll
        for (int u = 0; u < 4; u++)
            E[u] = __ldcs(&st4[(size_t)(wid + u * 16) * 32 + lane]);

        for (int i = 0; i < 256; i += 4) {
            float4 En[4];
            {
                int ibase = (i + 4 < 256) ? (i + 4) : 0;   // safe dummy prefetch on last iter
                #pragma unroll
                for (int u = 0; u < 4; u++)
                    En[u] = __ldcs(&st4[(size_t)(wid + (ibase + u) * 16) * 32 + lane]);
            }
            #pragma unroll
            for (int u = 0; u < 4; u++) {
                const int t = wid + (i + u) * 16;
                const float4 e = E[u];
                float p[8];
                #pragma unroll
                for (int h = 0; h < 8; h++)
                    p[h] = fmaf(e.x, wreg[0][h],
                           fmaf(e.y, wreg[1][h],
                           fmaf(e.z, wreg[2][h], e.w * wreg[3][h])));
                // multi-value butterfly: 8 head sums in 9 shfls
                const bool hi = (lane & 16);
                #pragma unroll
                for (int j = 0; j < 4; j++) {
                    float give = hi ? p[j]     : p[j + 4];
                    float keep = hi ? p[j + 4] : p[j];
                    p[j] = keep + __shfl_xor_sync(0xffffffffu, give, 16);
                }
                const bool m8 = (lane & 8);
                #pragma unroll
                for (int j = 0; j < 2; j++) {
                    float give = m8 ? p[j]     : p[j + 2];
                    float keep = m8 ? p[j + 2] : p[j];
                    p[j] = keep + __shfl_xor_sync(0xffffffffu, give, 8);
                }
                {
                    const bool m4 = (lane & 4);
                    float give = m4 ? p[0] : p[1];
                    float keep = m4 ? p[1] : p[0];
                    p[0] = keep + __shfl_xor_sync(0xffffffffu, give, 4);
                }
                p[0] += __shfl_xor_sync(0xffffffffu, p[0], 2);
                p[0] += __shfl_xor_sync(0xffffffffu, p[0], 1);
                if ((lane & 3) == 0) {
                    const int h = lane >> 2;          // lane 4m holds head m
                    const int q = t >> 9, k = t & 511;
                    scores[(q * 8 + h) * SC_PITCH + k] += p[0];
                }
            }
            #pragma unroll
            for (int u = 0; u < 4; u++) E[u] = En[u];
        }
    }
    __syncthreads();

    // ---------------- Phase 3: softmax per (q,h) row ----------------
    for (int r = wid; r < 64; r += 16) {
        float* srow = scores + r * SC_PITCH;   // r == q*8+h, layout matches
        float vals[16];
        float mx = -1e30f;
        #pragma unroll
        for (int j = 0; j < 16; j++) {
            int k = lane + 32 * j;
            float v = srow[k] + mask_s[k];
            vals[j] = v;
            mx = fmaxf(mx, v);
        }
        #pragma unroll
        for (int o = 16; o > 0; o >>= 1) mx = fmaxf(mx, __shfl_xor_sync(0xffffffffu, mx, o));
        float sum = 0.f;
        #pragma unroll
        for (int j = 0; j < 16; j++) {
            float e = __expf(vals[j] - mx);
            srow[lane + 32 * j] = e;       // store unnormalized exp
            sum += e;
        }
        #pragma unroll
        for (int o = 16; o > 0; o >>= 1) sum += __shfl_xor_sync(0xffffffffu, sum, o);
        if (lane == 0) rinv_s[r] = 1.0f / sum;
    }
    __syncthreads();

    // ---------------- Phase 4: PV ----------------
    float* outp = ks;   // reuse: [2][8][8][16]
    {
        const int h  = wid & 7;
        const int kh = wid >> 3;       // k-half -> each v row read once per block
        const int e  = lane & 15;
        const int kk = lane >> 4;
        const float* vbase = g_v + (size_t)(b * SS) * DD + h * 16 + e;
        float acc[8];
        #pragma unroll
        for (int q = 0; q < 8; q++) acc[q] = 0.f;
        const int kend = kh * 256 + 256;
        for (int k = kh * 256 + kk; k < kend; k += 2) {
            float vv = vbase[(size_t)k * DD];
            #pragma unroll
            for (int q = 0; q < 8; q++)
                acc[q] = fmaf(scores[(q * 8 + h) * SC_PITCH + k], vv, acc[q]);
        }
        #pragma unroll
        for (int q = 0; q < 8; q++) acc[q] += __shfl_xor_sync(0xffffffffu, acc[q], 16);
        if (lane < 16) {
            #pragma unroll
            for (int q = 0; q < 8; q++)
                outp[((kh * 8 + h) * 8 + q) * 16 + e] = acc[q];
        }
    }
    __syncthreads();

    // combine halves, normalize, store
    #pragma unroll
    for (int id = tid; id < 1024; id += 512) {
        int e = id & 15, q = (id >> 4) & 7, h = id >> 7;
        float val = (outp[((0 * 8 + h) * 8 + q) * 16 + e] +
                     outp[((1 * 8 + h) * 8 + q) * 16 + e]) * rinv_s[q * 8 + h];
        g_attn[(size_t)(b * SS + q0 + q) * DD + h * 16 + e] = val;
    }
}

// ---------------------------------------------------------------------------
// Kernel C: out = LN(residual + attn @ wo + bo). grid=256 (8 rows), block=256
// ---------------------------------------------------------------------------
__global__ __launch_bounds__(256) void out_ln_kernel(
    const float* __restrict__ x, const float* __restrict__ wo,
    const float* __restrict__ bo, const float* __restrict__ g,
    const float* __restrict__ bbeta, float* __restrict__ out)
{
    __shared__ float as_[8][128];
    __shared__ float ys[8][128];
    const int row0 = blockIdx.x * 8;
    const int t = threadIdx.x;

    ((float4*)as_)[t] = ((const float4*)(g_attn + (size_t)row0 * DD))[t];
    __syncthreads();

    const int c  = t & 127;
    const int rg = t >> 7;   // rows rg*4 .. rg*4+3
    float acc[4] = {0.f, 0.f, 0.f, 0.f};
    #pragma unroll 8
    for (int d = 0; d < 128; d++) {
        float w = wo[d * 128 + c];
        #pragma unroll
        for (int r = 0; r < 4; r++) acc[r] = fmaf(as_[rg * 4 + r][d], w, acc[r]);
    }
    float bias = bo[c];
    #pragma unroll
    for (int r = 0; r < 4; r++)
        ys[rg * 4 + r][c] = acc[r] + bias + x[(size_t)(row0 + rg * 4 + r) * DD + c];
    __syncthreads();

    // LayerNorm: 8 warps, 1 row each
    const int wid = t >> 5, lane = t & 31;
    float4 v = ((float4*)ys[wid])[lane];
    float s = v.x + v.y + v.z + v.w;
    #pragma unroll
    for (int o = 16; o > 0; o >>= 1) s += __shfl_xor_sync(0xffffffffu, s, o);
    float mu = s * (1.f / 128.f);
    float dx = v.x - mu, dy = v.y - mu, dz = v.z - mu, dw = v.w - mu;
    float ss = dx * dx + dy * dy + dz * dz + dw * dw;
    #pragma unroll
    for (int o = 16; o > 0; o >>= 1) ss += __shfl_xor_sync(0xffffffffu, ss, o);
    float rstd = rsqrtf(ss * (1.f / 128.f) + 1e-5f);
    float4 gg = ((const float4*)g)[lane];
    float4 bb = ((const float4*)bbeta)[lane];
    float4 o4;
    o4.x = dx * rstd * gg.x + bb.x;
    o4.y = dy * rstd * gg.y + bb.y;
    o4.z = dz * rstd * gg.z + bb.z;
    o4.w = dw * rstd * gg.w + bb.w;
    ((float4*)(out + (size_t)(row0 + wid) * DD))[lane] = o4;
}

// ---------------------------------------------------------------------------
extern "C" void kernel_launch(void* const* d_in, const int* in_sizes, int n_in,
                              void* d_out, int out_size)
{
    const float* x    = (const float*)d_in[0];
    const float* st   = (const float*)d_in[1];
    const int*   mask = (const int*)  d_in[2];
    const float* wq   = (const float*)d_in[3];
    const float* bq   = (const float*)d_in[4];
    const float* wk   = (const float*)d_in[5];
    const float* bk   = (const float*)d_in[6];
    const float* wv   = (const float*)d_in[7];
    const float* bv   = (const float*)d_in[8];
    const float* wo   = (const float*)d_in[9];
    const float* bo   = (const float*)d_in[10];
    const float* wst  = (const float*)d_in[11];
    const float* lng  = (const float*)d_in[12];
    const float* lnb  = (const float*)d_in[13];
    float* out = (float*)d_out;

    const int SMEM_B = (8 * 8 * SC_PITCH + 8 * 128 + 512 + 64 + 64 * 129) * 4;
    cudaFuncSetAttribute(attn_kernel, cudaFuncAttributeMaxDynamicSharedMemorySize, SMEM_B);

    qkv_kernel<<<256, 384>>>(x, wq, bq, wk, bk, wv, bv);
    attn_kernel<<<256, 512, SMEM_B>>>(st, mask, wst);
    out_ln_kernel<<<256, 256>>>(x, wo, bo, lng, lnb, out);
}

// round 2
// speedup vs baseline: 1.0009x; 1.0009x over previous
#include <cuda_runtime.h>
#include <cstdint>

#define BB 4
#define SS 512
#define DD 128
#define HH 8
#define SC_PITCH 516   // 516 % 32 == 4 -> 8 head lanes (stride 4 banks) conflict-free

// scratch (static device memory; no runtime allocation)
__device__ float g_q[BB*SS*DD];
__device__ float g_k[BB*SS*DD];
__device__ float g_v[BB*SS*DD];
__device__ float g_attn[BB*SS*DD];

// ---------------------------------------------------------------------------
// Kernel A: QKV projection. grid=256 (8 rows/block), block=384 (128 per matrix)
// ---------------------------------------------------------------------------
__global__ __launch_bounds__(384) void qkv_kernel(
    const float* __restrict__ x,
    const float* __restrict__ wq, const float* __restrict__ bq,
    const float* __restrict__ wk, const float* __restrict__ bk,
    const float* __restrict__ wv, const float* __restrict__ bv)
{
    __shared__ float xs[8][128];
    const int row0 = blockIdx.x * 8;
    const int t = threadIdx.x;

    if (t < 256) ((float4*)xs)[t] = ((const float4*)(x + (size_t)row0 * DD))[t];
    __syncthreads();

    const int mat = t >> 7;      // 0=q 1=k 2=v
    const int c   = t & 127;
    const float* W    = (mat == 0) ? wq : (mat == 1) ? wk : wv;
    const float* bias = (mat == 0) ? bq : (mat == 1) ? bk : bv;
    float* out        = (mat == 0) ? g_q : (mat == 1) ? g_k : g_v;

    float acc[8];
    #pragma unroll
    for (int r = 0; r < 8; r++) acc[r] = 0.f;

    #pragma unroll 8
    for (int d = 0; d < 128; d++) {
        float w = W[d * 128 + c];
        #pragma unroll
        for (int r = 0; r < 8; r++) acc[r] = fmaf(xs[r][d], w, acc[r]);
    }
    float bv_ = bias[c];
    #pragma unroll
    for (int r = 0; r < 8; r++) out[(size_t)(row0 + r) * DD + c] = acc[r] + bv_;
}

// ---------------------------------------------------------------------------
// Kernel B: fused st-bias + attention.
// grid = 256 (b = bx>>6, q0 = (bx&63)*8), block = 512, ~172KB dyn smem
// ---------------------------------------------------------------------------
__global__ __launch_bounds__(512, 1) void attn_kernel(
    const float* __restrict__ st, const int* __restrict__ mask,
    const float* __restrict__ wst)
{
    extern __shared__ float smem[];
    float* scores = smem;                               // [8][8][SC_PITCH]
    float* qs     = scores + 8 * 8 * SC_PITCH;          // [8][128]
    float* mask_s = qs + 8 * 128;                       // [512]
    float* rinv_s = mask_s + 512;                       // [64] (q*8+h)
    float* ks     = rinv_s + 64;                        // [64][129]; reused as outp[2][8][8][16]

    const int tid  = threadIdx.x;
    const int lane = tid & 31;
    const int wid  = tid >> 5;
    const int b    = blockIdx.x >> 6;
    const int q0   = (blockIdx.x & 63) * 8;

    // wst into registers: this lane owns d = 4*lane .. 4*lane+3
    float wreg[4][8];
    #pragma unroll
    for (int dd = 0; dd < 4; dd++)
        #pragma unroll
        for (int h = 0; h < 8; h++)
            wreg[dd][h] = wst[(4 * lane + dd) * HH + h];

    // stage q tile + mask
    if (tid < 256)
        ((float4*)qs)[tid] = ((const float4*)(g_q + (size_t)(b * SS + q0) * DD))[tid];
    mask_s[tid] = mask[b * SS + tid] ? -10000.0f : 0.0f;
    __syncthreads();

    // ---------------- Phase 1: qk^T / 4 into scores ----------------
    {
        const int q  = tid >> 6;   // 0..7
        const int kl = tid & 63;   // 0..63
        for (int kc = 0; kc < 8; kc++) {
            const float4* kg = (const float4*)(g_k + (size_t)(b * SS + kc * 64) * DD);
            #pragma unroll
            for (int idx = tid; idx < 64 * 32; idx += 512) {
                int r = idx >> 5, c4 = idx & 31;
                float4 kv = kg[r * 32 + c4];
                float* dst = ks + r * 129 + c4 * 4;
                dst[0] = kv.x; dst[1] = kv.y; dst[2] = kv.z; dst[3] = kv.w;
            }
            __syncthreads();

            float acc[8];
            #pragma unroll
            for (int h = 0; h < 8; h++) acc[h] = 0.f;
            const float* krow = ks + kl * 129;
            const float* qrow = qs + q * 128;
            #pragma unroll
            for (int e = 0; e < 128; e++)
                acc[e >> 4] = fmaf(qrow[e], krow[e], acc[e >> 4]);

            float* sdst = scores + (q * 8) * SC_PITCH + kc * 64 + kl;
            #pragma unroll
            for (int h = 0; h < 8; h++) sdst[h * SC_PITCH] = acc[h] * 0.25f;
            __syncthreads();
        }
    }

    // ---------------- Phase 2: st_emb bias (the 536MB stream) ----------------
    {
        // row (q*512+k) == task t; address = base + t*128 floats
        const float4* st4 = (const float4*)st + ((size_t)(b * SS + q0)) * SS * (DD / 4);
        float4 E[4];
        #pragma unroll
        for (int u = 0; u < 4; u++)
            E[u] = __ldcs(&st4[(size_t)(wid + u * 16) * 32 + lane]);

        for (int i = 0; i < 256; i += 4) {
            float4 En[4];
            {
                int ibase = (i + 4 < 256) ? (i + 4) : 0;   // safe dummy prefetch on last iter
                #pragma unroll
                for (int u = 0; u < 4; u++)
                    En[u] = __ldcs(&st4[(size_t)(wid + (ibase + u) * 16) * 32 + lane]);
            }
            #pragma unroll
            for (int u = 0; u < 4; u++) {
                const int t = wid + (i + u) * 16;
                const float4 e = E[u];
                float p[8];
                #pragma unroll
                for (int h = 0; h < 8; h++)
                    p[h] = fmaf(e.x, wreg[0][h],
                           fmaf(e.y, wreg[1][h],
                           fmaf(e.z, wreg[2][h], e.w * wreg[3][h])));
                // multi-value butterfly: 8 head sums in 9 shfls
                const bool hi = (lane & 16);
                #pragma unroll
                for (int j = 0; j < 4; j++) {
                    float give = hi ? p[j]     : p[j + 4];
                    float keep = hi ? p[j + 4] : p[j];
                    p[j] = keep + __shfl_xor_sync(0xffffffffu, give, 16);
                }
                const bool m8 = (lane & 8);
                #pragma unroll
                for (int j = 0; j < 2; j++) {
                    float give = m8 ? p[j]     : p[j + 2];
                    float keep = m8 ? p[j + 2] : p[j];
                    p[j] = keep + __shfl_xor_sync(0xffffffffu, give, 8);
                }
                {
                    const bool m4 = (lane & 4);
                    float give = m4 ? p[0] : p[1];
                    float keep = m4 ? p[1] : p[0];
                    p[0] = keep + __shfl_xor_sync(0xffffffffu, give, 4);
                }
                p[0] += __shfl_xor_sync(0xffffffffu, p[0], 2);
                p[0] += __shfl_xor_sync(0xffffffffu, p[0], 1);
                if ((lane & 3) == 0) {
                    const int h = lane >> 2;          // lane 4m holds head m
                    const int q = t >> 9, k = t & 511;
                    scores[(q * 8 + h) * SC_PITCH + k] += p[0];
                }
            }
            #pragma unroll
            for (int u = 0; u < 4; u++) E[u] = En[u];
        }
    }
    __syncthreads();

    // ---------------- Phase 3: softmax per (q,h) row ----------------
    for (int r = wid; r < 64; r += 16) {
        float* srow = scores + r * SC_PITCH;   // r == q*8+h, layout matches
        float vals[16];
        float mx = -1e30f;
        #pragma unroll
        for (int j = 0; j < 16; j++) {
            int k = lane + 32 * j;
            float v = srow[k] + mask_s[k];
            vals[j] = v;
            mx = fmaxf(mx, v);
        }
        #pragma unroll
        for (int o = 16; o > 0; o >>= 1) mx = fmaxf(mx, __shfl_xor_sync(0xffffffffu, mx, o));
        float sum = 0.f;
        #pragma unroll
        for (int j = 0; j < 16; j++) {
            float e = __expf(vals[j] - mx);
            srow[lane + 32 * j] = e;       // store unnormalized exp
            sum += e;
        }
        #pragma unroll
        for (int o = 16; o > 0; o >>= 1) sum += __shfl_xor_sync(0xffffffffu, sum, o);
        if (lane == 0) rinv_s[r] = 1.0f / sum;
    }
    __syncthreads();

    // ---------------- Phase 4: PV ----------------
    float* outp = ks;   // reuse: [2][8][8][16]
    {
        const int h  = wid & 7;
        const int kh = wid >> 3;       // k-half -> each v row read once per block
        const int e  = lane & 15;
        const int kk = lane >> 4;
        const float* vbase = g_v + (size_t)(b * SS) * DD + h * 16 + e;
        float acc[8];
        #pragma unroll
        for (int q = 0; q < 8; q++) acc[q] = 0.f;
        const int kend = kh * 256 + 256;
        for (int k = kh * 256 + kk; k < kend; k += 2) {
            float vv = vbase[(size_t)k * DD];
            #pragma unroll
            for (int q = 0; q < 8; q++)
                acc[q] = fmaf(scores[(q * 8 + h) * SC_PITCH + k], vv, acc[q]);
        }
        #pragma unroll
        for (int q = 0; q < 8; q++) acc[q] += __shfl_xor_sync(0xffffffffu, acc[q], 16);
        if (lane < 16) {
            #pragma unroll
            for (int q = 0; q < 8; q++)
                outp[((kh * 8 + h) * 8 + q) * 16 + e] = acc[q];
        }
    }
    __syncthreads();

    // combine halves, normalize, store
    #pragma unroll
    for (int id = tid; id < 1024; id += 512) {
        int e = id & 15, q = (id >> 4) & 7, h = id >> 7;
        float val = (outp[((0 * 8 + h) * 8 + q) * 16 + e] +
                     outp[((1 * 8 + h) * 8 + q) * 16 + e]) * rinv_s[q * 8 + h];
        g_attn[(size_t)(b * SS + q0 + q) * DD + h * 16 + e] = val;
    }
}

// ---------------------------------------------------------------------------
// Kernel C: out = LN(residual + attn @ wo + bo). grid=256 (8 rows), block=256
// ---------------------------------------------------------------------------
__global__ __launch_bounds__(256) void out_ln_kernel(
    const float* __restrict__ x, const float* __restrict__ wo,
    const float* __restrict__ bo, const float* __restrict__ g,
    const float* __restrict__ bbeta, float* __restrict__ out)
{
    __shared__ float as_[8][128];
    __shared__ float ys[8][128];
    const int row0 = blockIdx.x * 8;
    const int t = threadIdx.x;

    ((float4*)as_)[t] = ((const float4*)(g_attn + (size_t)row0 * DD))[t];
    __syncthreads();

    const int c  = t & 127;
    const int rg = t >> 7;   // rows rg*4 .. rg*4+3
    float acc[4] = {0.f, 0.f, 0.f, 0.f};
    #pragma unroll 8
    for (int d = 0; d < 128; d++) {
        float w = wo[d * 128 + c];
        #pragma unroll
        for (int r = 0; r < 4; r++) acc[r] = fmaf(as_[rg * 4 + r][d], w, acc[r]);
    }
    float bias = bo[c];
    #pragma unroll
    for (int r = 0; r < 4; r++)
        ys[rg * 4 + r][c] = acc[r] + bias + x[(size_t)(row0 + rg * 4 + r) * DD + c];
    __syncthreads();

    // LayerNorm: 8 warps, 1 row each
    const int wid = t >> 5, lane = t & 31;
    float4 v = ((float4*)ys[wid])[lane];
    float s = v.x + v.y + v.z + v.w;
    #pragma unroll
    for (int o = 16; o > 0; o >>= 1) s += __shfl_xor_sync(0xffffffffu, s, o);
    float mu = s * (1.f / 128.f);
    float dx = v.x - mu, dy = v.y - mu, dz = v.z - mu, dw = v.w - mu;
    float ss = dx * dx + dy * dy + dz * dz + dw * dw;
    #pragma unroll
    for (int o = 16; o > 0; o >>= 1) ss += __shfl_xor_sync(0xffffffffu, ss, o);
    float rstd = rsqrtf(ss * (1.f / 128.f) + 1e-5f);
    float4 gg = ((const float4*)g)[lane];
    float4 bb = ((const float4*)bbeta)[lane];
    float4 o4;
    o4.x = dx * rstd * gg.x + bb.x;
    o4.y = dy * rstd * gg.y + bb.y;
    o4.z = dz * rstd * gg.z + bb.z;
    o4.w = dw * rstd * gg.w + bb.w;
    ((float4*)(out + (size_t)(row0 + wid) * DD))[lane] = o4;
}

// ---------------------------------------------------------------------------
extern "C" void kernel_launch(void* const* d_in, const int* in_sizes, int n_in,
                              void* d_out, int out_size)
{
    const float* x    = (const float*)d_in[0];
    const float* st   = (const float*)d_in[1];
    const int*   mask = (const int*)  d_in[2];
    const float* wq   = (const float*)d_in[3];
    const float* bq   = (const float*)d_in[4];
    const float* wk   = (const float*)d_in[5];
    const float* bk   = (const float*)d_in[6];
    const float* wv   = (const float*)d_in[7];
    const float* bv   = (const float*)d_in[8];
    const float* wo   = (const float*)d_in[9];
    const float* bo   = (const float*)d_in[10];
    const float* wst  = (const float*)d_in[11];
    const float* lng  = (const float*)d_in[12];
    const float* lnb  = (const float*)d_in[13];
    float* out = (float*)d_out;

    const int SMEM_B = (8 * 8 * SC_PITCH + 8 * 128 + 512 + 64 + 64 * 129) * 4;
    cudaFuncSetAttribute(attn_kernel, cudaFuncAttributeMaxDynamicSharedMemorySize, SMEM_B);

    qkv_kernel<<<256, 384>>>(x, wq, bq, wk, bk, wv, bv);
    attn_kernel<<<256, 512, SMEM_B>>>(st, mask, wst);
    out_ln_kernel<<<256, 256>>>(x, wo, bo, lng, lnb, out);
}